// round 1
// baseline (speedup 1.0000x reference)
#include <cuda_runtime.h>
#include <cuda_bf16.h>

// CapsuleLayer: x[8,2048,512], W[32,512,64] -> nodes[8,32,64]
// Fused routing: capsules tensor is never materialized.
//   nodes = (sum_s r*x) @ W[n];  agreement = x . (W[n] @ tanh(nodes))

#define BB 8
#define SS 2048
#define II 512
#define NN 32
#define DD 64
#define TS 64   // s-rows per fused block

typedef unsigned long long ull;

__device__ float g_xsum[BB*II];
__device__ float g_y[BB*NN*II];
__device__ float g_U[BB*II*NN];   // packed layout: [b][i/2][n][2]
__device__ float g_b1[BB*SS*NN];

__device__ __forceinline__ void ffma2(ull &d, ull a, ull b){
    asm("fma.rn.f32x2 %0, %1, %2, %0;" : "+l"(d) : "l"(a), "l"(b));
}
__device__ __forceinline__ ull pack2(float lo, float hi){
    ull r; asm("mov.b64 %0, {%1, %2};" : "=l"(r) : "f"(lo), "f"(hi)); return r;
}
__device__ __forceinline__ float2 unpack2(ull v){
    float2 r; asm("mov.b64 {%0, %1}, %2;" : "=f"(r.x), "=f"(r.y) : "l"(v)); return r;
}

// ---------------------------------------------------------------- zero scratch
__global__ void zero_kernel(int which){
    int i = blockIdx.x*blockDim.x + threadIdx.x;
    if (which == 0){ if (i < BB*II) g_xsum[i] = 0.f; }
    else           { if (i < BB*NN*II) g_y[i] = 0.f; }
}

// ---------------------------------------------------------------- xsum = sum_s x
__global__ void xsum_kernel(const float* __restrict__ x){
    int b = blockIdx.y, c = blockIdx.x, tid = threadIdx.x;   // grid (32,8), 512 thr
    const float* xp = x + ((size_t)(b*SS + c*64))*II + tid;
    float acc = 0.f;
    #pragma unroll 8
    for (int r = 0; r < 64; r++) acc += xp[(size_t)r*II];
    atomicAdd(&g_xsum[b*II + tid], acc);
}

// ---------------------------------------------------------------- nodes/t/U update
// grid (NN, BB), 128 threads.  out!=null => final iteration: write nodes only.
__global__ void nodes_update_kernel(const float* __restrict__ W, float scale,
                                    int use_xsum, float* __restrict__ out){
    int n = blockIdx.x, b = blockIdx.y, tid = threadIdx.x;
    __shared__ float ys[II];
    __shared__ float tsm[DD];
    const float* src = use_xsum ? (g_xsum + b*II) : (g_y + (size_t)(b*NN + n)*II);
    for (int i = tid; i < II; i += blockDim.x) ys[i] = src[i];
    __syncthreads();
    if (tid < DD){
        const float* Wn = W + (size_t)n*II*DD + tid;   // W[n][i][tid], stride DD
        float acc = 0.f;
        #pragma unroll 8
        for (int i = 0; i < II; i++) acc += ys[i] * Wn[(size_t)i*DD];
        float nd = acc * scale;
        if (out) out[(size_t)(b*NN + n)*DD + tid] = nd;
        else     tsm[tid] = tanhf(nd);
    }
    __syncthreads();
    if (!out){
        for (int i = tid; i < II; i += blockDim.x){
            const float4* Wr = (const float4*)(W + ((size_t)n*II + i)*DD);
            float acc = 0.f;
            #pragma unroll
            for (int d4 = 0; d4 < 16; d4++){
                float4 w = Wr[d4];
                acc += w.x*tsm[4*d4] + w.y*tsm[4*d4+1] + w.z*tsm[4*d4+2] + w.w*tsm[4*d4+3];
            }
            // packed pair layout for conflict-free f32x2 smem loads later
            g_U[(size_t)b*(II*NN) + (i>>1)*(2*NN) + n*2 + (i&1)] = acc;
        }
    }
}

// ---------------------------------------------------------------- fused routing pass
// Per s-row: a[n] = x.U[n] (+ b_prev), r = softmax_n(a), y[n,:] += r[n]*x
// grid (SS/TS, BB), 256 threads, 200KB dynamic smem.
__global__ void __launch_bounds__(256, 1)
fused_pass_kernel(const float* __restrict__ x, int pass_c){
    extern __shared__ float smem[];
    float* sX = smem;             // TS*II  = 32768 floats
    float* sU = sX + TS*II;       // II*NN  = 16384 floats (packed pairs)
    float* sR = sU + II*NN;       // TS*NN  =  2048 floats
    int tile = blockIdx.x, b = blockIdx.y, tid = threadIdx.x;
    int s0 = tile*TS;

    // ---- stage x tile + U (both coalesced, float4)
    const float* xt = x + ((size_t)(b*SS + s0))*II;
    for (int idx = tid; idx < TS*II/4; idx += 256)
        ((float4*)sX)[idx] = ((const float4*)xt)[idx];
    const float* Ub = g_U + (size_t)b*(II*NN);
    for (int idx = tid; idx < II*NN/4; idx += 256)
        ((float4*)sU)[idx] = ((const float4*)Ub)[idx];
    __syncthreads();

    // ---- phase 1: agreement + softmax. warp w handles rows [8w,8w+8), lane = n
    int warp = tid >> 5, lane = tid & 31;
    int row0 = warp * 8;
    ull a2[8];
    #pragma unroll
    for (int r = 0; r < 8; r++) a2[r] = 0ULL;
    const ull* U64 = (const ull*)sU;        // U64[i2*NN + n] = pair (2*i2, 2*i2+1)
    #pragma unroll 4
    for (int i2 = 0; i2 < II/2; i2 += 2){
        ull u0 = U64[i2*NN + lane];
        ull u1 = U64[(i2+1)*NN + lane];
        #pragma unroll
        for (int rr = 0; rr < 8; rr++){
            const ulonglong2 xv = *(const ulonglong2*)&sX[(row0+rr)*II + i2*2];
            ffma2(a2[rr], xv.x, u0);
            ffma2(a2[rr], xv.y, u1);
        }
    }
    #pragma unroll
    for (int rr = 0; rr < 8; rr++){
        float2 p = unpack2(a2[rr]);
        float a = p.x + p.y;
        int row = row0 + rr;
        int gidx = ((b*SS) + s0 + row)*NN + lane;
        if (pass_c) a += g_b1[gidx];
        else        g_b1[gidx] = a;
        float m = a;
        #pragma unroll
        for (int off = 16; off > 0; off >>= 1)
            m = fmaxf(m, __shfl_xor_sync(0xffffffffu, m, off));
        float e = __expf(a - m);
        float ssum = e;
        #pragma unroll
        for (int off = 16; off > 0; off >>= 1)
            ssum += __shfl_xor_sync(0xffffffffu, ssum, off);
        sR[row*NN + lane] = e / ssum;
    }
    __syncthreads();

    // ---- phase 2: y[n,i] += sum_ts r[ts,n]*x[ts,i]
    // thread: n = tid/8, i in { (tid&7)*4 + 32k + j : k<16, j<4 }  (bank-spread)
    int n = tid >> 3, col = tid & 7;
    ull acc[32];
    #pragma unroll
    for (int p = 0; p < 32; p++) acc[p] = 0ULL;
    for (int ts = 0; ts < TS; ts++){
        float rv = sR[ts*NN + n];
        ull rvv = pack2(rv, rv);
        const float* xr = &sX[ts*II + col*4];
        #pragma unroll
        for (int k = 0; k < 16; k++){
            const ulonglong2 xv = *(const ulonglong2*)&xr[32*k];
            ffma2(acc[2*k],   xv.x, rvv);
            ffma2(acc[2*k+1], xv.y, rvv);
        }
    }
    float* yb = g_y + (size_t)(b*NN + n)*II;
    #pragma unroll
    for (int k = 0; k < 16; k++){
        float2 p0 = unpack2(acc[2*k]);
        float2 p1 = unpack2(acc[2*k+1]);
        int i0 = col*4 + 32*k;
        atomicAdd(&yb[i0],   p0.x);
        atomicAdd(&yb[i0+1], p0.y);
        atomicAdd(&yb[i0+2], p1.x);
        atomicAdd(&yb[i0+3], p1.y);
    }
}

// ---------------------------------------------------------------- launch
extern "C" void kernel_launch(void* const* d_in, const int* in_sizes, int n_in,
                              void* d_out, int out_size){
    const float* x = (const float*)d_in[0];
    const float* W = (const float*)d_in[1];
    float* out = (float*)d_out;

    const size_t shmem = (size_t)(TS*II + II*NN + TS*NN) * sizeof(float);  // 204800
    cudaFuncSetAttribute(fused_pass_kernel,
                         cudaFuncAttributeMaxDynamicSharedMemorySize, (int)shmem);

    // it 0: r uniform -> nodes0 from xsum
    zero_kernel<<<16, 256>>>(0);
    xsum_kernel<<<dim3(32, BB), 512>>>(x);
    nodes_update_kernel<<<dim3(NN, BB), 128>>>(W, 1.0f/32.0f, 1, nullptr);

    // it 1: b1 = agreement0, r1 = softmax(b1), y1 = sum r1*x
    zero_kernel<<<512, 256>>>(1);
    fused_pass_kernel<<<dim3(SS/TS, BB), 256, shmem>>>(x, 0);
    nodes_update_kernel<<<dim3(NN, BB), 128>>>(W, 1.0f, 0, nullptr);

    // it 2: b2 = b1 + agreement1, r2 = softmax(b2), y2 = sum r2*x -> nodes2 = out
    zero_kernel<<<512, 256>>>(1);
    fused_pass_kernel<<<dim3(SS/TS, BB), 256, shmem>>>(x, 1);
    nodes_update_kernel<<<dim3(NN, BB), 128>>>(W, 1.0f, 0, out);
}

// round 3
// speedup vs baseline: 1.4634x; 1.4634x over previous
#include <cuda_runtime.h>

// CapsuleLayer: x[8,2048,512], W[32,512,64] -> nodes[8,32,64]
// Fused routing, capsules never materialized:
//   nodes = (sum_s r*x) @ W[n];  agreement = x . (W[n] @ tanh(nodes))

#define BB 8
#define SS 2048
#define II 512
#define NN 32
#define DD 64
#define TS 64    // s-rows per fused block
#define PP 32    // xsum partial slabs

typedef unsigned long long ull;

__device__ __align__(16) float g_xsumP[PP*BB*II];
__device__ __align__(16) float g_y[BB*NN*II];
__device__ __align__(16) float g_U[BB*II*NN];   // [b][i>>2][n][i&3]
__device__ float g_b1[BB*SS*NN];

__device__ __forceinline__ void ffma2(ull &d, ull a, ull b){
    asm("fma.rn.f32x2 %0, %1, %2, %0;" : "+l"(d) : "l"(a), "l"(b));
}
__device__ __forceinline__ ull pack2(float lo, float hi){
    ull r; asm("mov.b64 %0, {%1, %2};" : "=l"(r) : "f"(lo), "f"(hi)); return r;
}
__device__ __forceinline__ float2 unpack2(ull v){
    float2 r; asm("mov.b64 {%0, %1}, %2;" : "=f"(r.x), "=f"(r.y) : "l"(v)); return r;
}

// ------------------------------------------------ xsum partials (no atomics)
__global__ void xsum_kernel(const float* __restrict__ x){
    int p = blockIdx.x, b = blockIdx.y, tid = threadIdx.x;   // grid (32,8), 512 thr
    const float* xp = x + ((size_t)(b*SS + p*(SS/PP)))*II + tid;
    float acc = 0.f;
    #pragma unroll 8
    for (int r = 0; r < SS/PP; r++) acc += xp[(size_t)r*II];
    g_xsumP[(size_t)(p*BB + b)*II + tid] = acc;
}

// ------------------------------------------------ nodes / tanh / U update
// grid (NN, BB), 256 threads. out!=null => final iter, write nodes only.
__global__ void nodes_update_kernel(const float* __restrict__ W, float scale,
                                    int use_xsum, float* __restrict__ out){
    int n = blockIdx.x, b = blockIdx.y, tid = threadIdx.x;
    __shared__ float ys[II];
    __shared__ float part[256];
    __shared__ float tsm[DD];

    if (use_xsum){
        for (int i = tid; i < II; i += 256){
            float a = 0.f;
            #pragma unroll 8
            for (int p = 0; p < PP; p++) a += g_xsumP[(size_t)(p*BB + b)*II + i];
            ys[i] = a;
        }
    } else {
        const float* src = g_y + (size_t)(b*NN + n)*II;
        for (int i = tid; i < II; i += 256) ys[i] = src[i];
    }
    __syncthreads();

    // part A: nd[d] = sum_i ys[i]*W[n][i][d], K split 4-way
    {
        int d = tid & 63, ch = tid >> 6;
        const float* Wn = W + (size_t)n*II*DD + d;
        float acc = 0.f;
        int i0 = ch*128;
        #pragma unroll 8
        for (int i = 0; i < 128; i++) acc += ys[i0+i] * Wn[(size_t)(i0+i)*DD];
        part[tid] = acc;
    }
    __syncthreads();
    if (tid < DD){
        float nd = (part[tid] + part[64+tid] + part[128+tid] + part[192+tid]) * scale;
        if (out) out[(size_t)(b*NN + n)*DD + tid] = nd;
        else     tsm[tid] = tanhf(nd);
    }
    __syncthreads();

    // part B: U[i] = W[n][i][:] . tanh(nd);  also zero g_y for next pass
    if (!out){
        for (int i = tid; i < II; i += 256){
            const float4* Wr = (const float4*)(W + ((size_t)n*II + i)*DD);
            float acc = 0.f;
            #pragma unroll
            for (int d4 = 0; d4 < 16; d4++){
                float4 w = Wr[d4];
                acc += w.x*tsm[4*d4] + w.y*tsm[4*d4+1] + w.z*tsm[4*d4+2] + w.w*tsm[4*d4+3];
            }
            g_U[(size_t)b*(II*NN) + (size_t)(i>>2)*(NN*4) + n*4 + (i&3)] = acc;
            g_y[(size_t)(b*NN + n)*II + i] = 0.f;
        }
    }
}

// ------------------------------------------------ fused routing pass
// a[n] = x.U[n] (+b_prev) -> softmax_n -> y[n,:] += r[n]*x
// grid (SS/TS, BB), 512 threads, 200KB dynamic smem.
__global__ void __launch_bounds__(512, 1)
fused_pass_kernel(const float* __restrict__ x, int pass_c){
    extern __shared__ float smem[];
    float* sX = smem;             // TS*II  = 32768 floats (128KB)
    float* sU = sX + TS*II;       // II*NN  = 16384 floats (64KB, quad layout)
    float* sR = sU + II*NN;       // TS*NN  =  2048 floats
    int tile = blockIdx.x, b = blockIdx.y, tid = threadIdx.x;
    int s0 = tile*TS;

    // stage x tile + U (coalesced float4)
    const float* xt = x + ((size_t)(b*SS + s0))*II;
    #pragma unroll
    for (int it = 0; it < TS*II/4/512; it++)
        ((float4*)sX)[it*512 + tid] = ((const float4*)xt)[it*512 + tid];
    const float* Ub = g_U + (size_t)b*(II*NN);
    #pragma unroll
    for (int it = 0; it < II*NN/4/512; it++)
        ((float4*)sU)[it*512 + tid] = ((const float4*)Ub)[it*512 + tid];
    __syncthreads();

    // ---- phase 1: agreement + softmax. warp w -> rows [4w,4w+4), lane = n
    {
        int warp = tid >> 5, lane = tid & 31;
        int row0 = warp * 4;
        ull a2[4] = {0ULL,0ULL,0ULL,0ULL};
        const ulonglong2* U2 = (const ulonglong2*)sU;   // [q*NN + n] -> 4 floats
        #pragma unroll 2
        for (int q = 0; q < II/4; q++){
            ulonglong2 u = U2[q*NN + lane];
            #pragma unroll
            for (int rr = 0; rr < 4; rr++){
                const ulonglong2 xv = *(const ulonglong2*)&sX[(row0+rr)*II + q*4];
                ffma2(a2[rr], xv.x, u.x);
                ffma2(a2[rr], xv.y, u.y);
            }
        }
        #pragma unroll
        for (int rr = 0; rr < 4; rr++){
            float2 p = unpack2(a2[rr]);
            float a = p.x + p.y;
            int row = row0 + rr;
            int gidx = ((b*SS) + s0 + row)*NN + lane;
            if (pass_c) a += g_b1[gidx];
            else        g_b1[gidx] = a;
            float m = a;
            #pragma unroll
            for (int off = 16; off > 0; off >>= 1)
                m = fmaxf(m, __shfl_xor_sync(0xffffffffu, m, off));
            float e = __expf(a - m);
            float ssum = e;
            #pragma unroll
            for (int off = 16; off > 0; off >>= 1)
                ssum += __shfl_xor_sync(0xffffffffu, ssum, off);
            sR[row*NN + lane] = e / ssum;
        }
    }
    __syncthreads();

    // ---- phase 2: y[n,i] += sum_ts r[ts,n]*x[ts,i]
    // thread: g=tid>>6 -> n in {g,g+8,g+16,g+24}; c=tid&63 -> i quads c*4+256k, k<2
    {
        int g = tid >> 6, c = tid & 63;
        ull acc[16];
        #pragma unroll
        for (int p = 0; p < 16; p++) acc[p] = 0ULL;
        for (int ts = 0; ts < TS; ts++){
            const float* rrow = &sR[ts*NN];
            ull rv0 = pack2(rrow[g],      rrow[g]);
            ull rv1 = pack2(rrow[g+8],  rrow[g+8]);
            ull rv2 = pack2(rrow[g+16], rrow[g+16]);
            ull rv3 = pack2(rrow[g+24], rrow[g+24]);
            #pragma unroll
            for (int k = 0; k < 2; k++){
                const ulonglong2 xv = *(const ulonglong2*)&sX[ts*II + c*4 + 256*k];
                ffma2(acc[k*8+0], xv.x, rv0); ffma2(acc[k*8+1], xv.y, rv0);
                ffma2(acc[k*8+2], xv.x, rv1); ffma2(acc[k*8+3], xv.y, rv1);
                ffma2(acc[k*8+4], xv.x, rv2); ffma2(acc[k*8+5], xv.y, rv2);
                ffma2(acc[k*8+6], xv.x, rv3); ffma2(acc[k*8+7], xv.y, rv3);
            }
        }
        #pragma unroll
        for (int j = 0; j < 4; j++){
            int n = g + 8*j;
            float* yb = g_y + (size_t)(b*NN + n)*II;
            #pragma unroll
            for (int k = 0; k < 2; k++){
                float2 p0 = unpack2(acc[k*8 + j*2]);
                float2 p1 = unpack2(acc[k*8 + j*2 + 1]);
                int i0 = c*4 + 256*k;
                atomicAdd(&yb[i0],   p0.x);
                atomicAdd(&yb[i0+1], p0.y);
                atomicAdd(&yb[i0+2], p1.x);
                atomicAdd(&yb[i0+3], p1.y);
            }
        }
    }
}

// ------------------------------------------------ launch (6 kernels)
extern "C" void kernel_launch(void* const* d_in, const int* in_sizes, int n_in,
                              void* d_out, int out_size){
    const float* x = (const float*)d_in[0];
    const float* W = (const float*)d_in[1];
    float* out = (float*)d_out;

    const size_t shmem = (size_t)(TS*II + II*NN + TS*NN) * sizeof(float);  // 204800
    cudaFuncSetAttribute(fused_pass_kernel,
                         cudaFuncAttributeMaxDynamicSharedMemorySize, (int)shmem);

    // it 0: r uniform -> nodes0 from xsum; nodes_update also zeroes g_y
    xsum_kernel<<<dim3(PP, BB), 512>>>(x);
    nodes_update_kernel<<<dim3(NN, BB), 256>>>(W, 1.0f/32.0f, 1, nullptr);

    // it 1
    fused_pass_kernel<<<dim3(SS/TS, BB), 512, shmem>>>(x, 0);
    nodes_update_kernel<<<dim3(NN, BB), 256>>>(W, 1.0f, 0, nullptr);

    // it 2
    fused_pass_kernel<<<dim3(SS/TS, BB), 512, shmem>>>(x, 1);
    nodes_update_kernel<<<dim3(NN, BB), 256>>>(W, 1.0f, 0, out);
}

// round 4
// speedup vs baseline: 1.8462x; 1.2615x over previous
#include <cuda_runtime.h>

// CapsuleLayer: x[8,2048,512], W[32,512,64] -> nodes[8,32,64]
// Fused routing, capsules never materialized:
//   nodes = (sum_s r*x) @ W[n];  agreement = x . (W[n] @ tanh(nodes))

#define BB 8
#define SS 2048
#define II 512
#define NN 32
#define DD 64
#define TS 64            // s-rows per fused block
#define NT (SS/TS)       // 32 tiles per b
#define PP 32            // xsum partial slabs

typedef unsigned long long ull;

__device__ __align__(16) float g_xsumP[PP*BB*II];
__device__ __align__(16) float g_yP[BB*NN*NT*II];   // per-tile y partials
__device__ __align__(16) float g_U[BB*II*NN];       // [b][i>>2][n][i&3]
__device__ float g_b1[BB*SS*NN];

__device__ __forceinline__ void ffma2(ull &d, ull a, ull b){
    asm("fma.rn.f32x2 %0, %1, %2, %0;" : "+l"(d) : "l"(a), "l"(b));
}
__device__ __forceinline__ ull pack2(float lo, float hi){
    ull r; asm("mov.b64 %0, {%1, %2};" : "=l"(r) : "f"(lo), "f"(hi)); return r;
}
__device__ __forceinline__ float2 unpack2(ull v){
    float2 r; asm("mov.b64 {%0, %1}, %2;" : "=f"(r.x), "=f"(r.y) : "l"(v)); return r;
}

// ------------------------------------------------ xsum partials (no atomics)
__global__ void xsum_kernel(const float* __restrict__ x){
    int p = blockIdx.x, b = blockIdx.y, tid = threadIdx.x;   // grid (PP,8), 512 thr
    const float* xp = x + ((size_t)(b*SS + p*(SS/PP)))*II + tid;
    float acc = 0.f;
    #pragma unroll 16
    for (int r = 0; r < SS/PP; r++) acc += xp[(size_t)r*II];
    g_xsumP[(size_t)(p*BB + b)*II + tid] = acc;
}

// ------------------------------------------------ nodes / tanh / U update
// grid (NN, BB), 512 threads. out!=null => final iter, write nodes only.
__global__ void __launch_bounds__(512)
nodes_update_kernel(const float* __restrict__ W, float scale,
                    int use_xsum, float* __restrict__ out){
    int n = blockIdx.x, b = blockIdx.y, tid = threadIdx.x;
    __shared__ float ys[II];
    __shared__ float sPart[32*68];   // padded: stride 68
    __shared__ float tsm[DD];

    // ---- load ys (xsum reduction OR y-partial reduction), high MLP
    if (tid < II){
        float a = 0.f;
        if (use_xsum){
            const float* p0 = g_xsumP + tid;
            #pragma unroll
            for (int p = 0; p < PP; p++) a += p0[(size_t)(p*BB + b)*II];
        } else {
            const float* p0 = g_yP + ((size_t)(b*NN + n)*NT)*II + tid;
            #pragma unroll
            for (int t = 0; t < NT; t++) a += p0[(size_t)t*II];
        }
        ys[tid] = a;
    }
    __syncthreads();

    // ---- part A: nd[d] = sum_i ys[i]*W[n][i][d]; thread = (ch, d4), MLP 16
    {
        int d4 = tid & 15, ch = tid >> 4;           // 16 d-quads x 32 i-chunks
        const float4* Wp = (const float4*)(W + ((size_t)n*II + ch*16)*DD) + d4;
        float4 acc = {0.f,0.f,0.f,0.f};
        #pragma unroll
        for (int j = 0; j < 16; j++){
            float yv = ys[ch*16 + j];
            float4 w = Wp[j*16];
            acc.x += yv*w.x; acc.y += yv*w.y; acc.z += yv*w.z; acc.w += yv*w.w;
        }
        float* sp = &sPart[ch*68 + d4*4];
        sp[0] = acc.x; sp[1] = acc.y; sp[2] = acc.z; sp[3] = acc.w;
    }
    __syncthreads();
    if (tid < DD){
        float nd = 0.f;
        #pragma unroll
        for (int ch = 0; ch < 32; ch++) nd += sPart[ch*68 + tid];
        nd *= scale;
        if (out) out[(size_t)(b*NN + n)*DD + tid] = nd;
        else     tsm[tid] = tanhf(nd);
    }
    __syncthreads();

    // ---- part B: U[b,n,i] = W[n][i][:] . tanh(nd); one i per thread
    if (!out && tid < II){
        int i = tid;
        const float4* Wr = (const float4*)(W + ((size_t)n*II + i)*DD);
        float acc = 0.f;
        #pragma unroll
        for (int d4 = 0; d4 < 16; d4++){
            float4 w = Wr[d4];
            acc += w.x*tsm[4*d4] + w.y*tsm[4*d4+1] + w.z*tsm[4*d4+2] + w.w*tsm[4*d4+3];
        }
        g_U[(size_t)b*(II*NN) + (size_t)(i>>2)*(NN*4) + n*4 + (i&3)] = acc;
    }
}

// ------------------------------------------------ fused routing pass
// a[n] = x.U[n] (+b_prev) -> softmax_n -> yP[tile][n,:] = sum r[n]*x
// grid (NT, BB), 512 threads, 216KB dynamic smem, no atomics.
__global__ void __launch_bounds__(512, 1)
fused_pass_kernel(const float* __restrict__ x, int pass_c){
    extern __shared__ float smem[];
    float* sX = smem;             // TS*II  = 32768 floats (128KB)
    float* sU = sX + TS*II;       // II*NN  = 16384 floats (64KB, quad layout)
    float* sR = sU + II*NN;       // TS*NN  =  2048 floats
    float* sP = sR + TS*NN;       // 2*TS*NN = 4096 floats (split-K partials)
    int tile = blockIdx.x, b = blockIdx.y, tid = threadIdx.x;
    int s0 = tile*TS;

    // ---- stage x tile + U (coalesced float4)
    const float* xt = x + ((size_t)(b*SS + s0))*II;
    #pragma unroll
    for (int it = 0; it < TS*II/4/512; it++)
        ((float4*)sX)[it*512 + tid] = ((const float4*)xt)[it*512 + tid];
    const float* Ub = g_U + (size_t)b*(II*NN);
    #pragma unroll
    for (int it = 0; it < II*NN/4/512; it++)
        ((float4*)sU)[it*512 + tid] = ((const float4*)Ub)[it*512 + tid];
    __syncthreads();

    // ---- phase 1a: agreement, split-K: group g=warp>>1 rows [8g,8g+8), half h=warp&1
    {
        int warp = tid >> 5, lane = tid & 31;
        int g = warp >> 1, h = warp & 1;
        int row0 = g*8, q0 = h*64;
        ull a2[8];
        #pragma unroll
        for (int r = 0; r < 8; r++) a2[r] = 0ULL;
        const ulonglong2* U2 = (const ulonglong2*)sU;   // [q*NN + n] -> 4 floats
        #pragma unroll 2
        for (int qq = 0; qq < 64; qq++){
            int q = q0 + qq;
            ulonglong2 u = U2[q*NN + lane];
            #pragma unroll
            for (int rr = 0; rr < 8; rr++){
                const ulonglong2 xv = *(const ulonglong2*)&sX[(row0+rr)*II + q*4];
                ffma2(a2[rr], xv.x, u.x);
                ffma2(a2[rr], xv.y, u.y);
            }
        }
        #pragma unroll
        for (int rr = 0; rr < 8; rr++){
            float2 p = unpack2(a2[rr]);
            sP[h*(TS*NN) + (row0+rr)*NN + lane] = p.x + p.y;
        }
    }
    __syncthreads();

    // ---- phase 1b: combine halves + softmax (warps with h==0, 8 rows each)
    {
        int warp = tid >> 5, lane = tid & 31;
        if ((warp & 1) == 0){
            int row0 = (warp >> 1)*8;
            #pragma unroll
            for (int rr = 0; rr < 8; rr++){
                int row = row0 + rr;
                float a = sP[row*NN + lane] + sP[TS*NN + row*NN + lane];
                int gidx = ((b*SS) + s0 + row)*NN + lane;
                if (pass_c) a += g_b1[gidx];
                else        g_b1[gidx] = a;
                float m = a;
                #pragma unroll
                for (int off = 16; off > 0; off >>= 1)
                    m = fmaxf(m, __shfl_xor_sync(0xffffffffu, m, off));
                float e = __expf(a - m);
                float ssum = e;
                #pragma unroll
                for (int off = 16; off > 0; off >>= 1)
                    ssum += __shfl_xor_sync(0xffffffffu, ssum, off);
                sR[row*NN + lane] = e / ssum;
            }
        }
    }
    __syncthreads();

    // ---- phase 2: yP[n,i] = sum_ts r[ts,n]*x[ts,i]
    // thread: g2=tid>>7 -> n in [8*g2, 8*g2+8); c=tid&127 -> floats [c*4, c*4+4)
    {
        int g2 = tid >> 7, c = tid & 127;
        int nb = g2*8;
        ull acc[16];
        #pragma unroll
        for (int p = 0; p < 16; p++) acc[p] = 0ULL;
        for (int ts = 0; ts < TS; ts++){
            // 8 r values for contiguous n: two LDS.128 broadcasts
            const ulonglong2 rA = *(const ulonglong2*)&sR[ts*NN + nb];
            const ulonglong2 rB = *(const ulonglong2*)&sR[ts*NN + nb + 4];
            float2 r01 = unpack2(rA.x), r23 = unpack2(rA.y);
            float2 r45 = unpack2(rB.x), r67 = unpack2(rB.y);
            ull rv0 = pack2(r01.x, r01.x), rv1 = pack2(r01.y, r01.y);
            ull rv2 = pack2(r23.x, r23.x), rv3 = pack2(r23.y, r23.y);
            ull rv4 = pack2(r45.x, r45.x), rv5 = pack2(r45.y, r45.y);
            ull rv6 = pack2(r67.x, r67.x), rv7 = pack2(r67.y, r67.y);
            const ulonglong2 xv = *(const ulonglong2*)&sX[ts*II + c*4];
            ffma2(acc[0],  xv.x, rv0); ffma2(acc[1],  xv.y, rv0);
            ffma2(acc[2],  xv.x, rv1); ffma2(acc[3],  xv.y, rv1);
            ffma2(acc[4],  xv.x, rv2); ffma2(acc[5],  xv.y, rv2);
            ffma2(acc[6],  xv.x, rv3); ffma2(acc[7],  xv.y, rv3);
            ffma2(acc[8],  xv.x, rv4); ffma2(acc[9],  xv.y, rv4);
            ffma2(acc[10], xv.x, rv5); ffma2(acc[11], xv.y, rv5);
            ffma2(acc[12], xv.x, rv6); ffma2(acc[13], xv.y, rv6);
            ffma2(acc[14], xv.x, rv7); ffma2(acc[15], xv.y, rv7);
        }
        // flush partials: coalesced STG.128, no atomics
        #pragma unroll
        for (int j = 0; j < 8; j++){
            float2 p0 = unpack2(acc[2*j]);
            float2 p1 = unpack2(acc[2*j+1]);
            float4 v = {p0.x, p0.y, p1.x, p1.y};
            *(float4*)&g_yP[(((size_t)(b*NN + nb + j))*NT + tile)*II + c*4] = v;
        }
    }
}

// ------------------------------------------------ launch (6 kernels)
extern "C" void kernel_launch(void* const* d_in, const int* in_sizes, int n_in,
                              void* d_out, int out_size){
    const float* x = (const float*)d_in[0];
    const float* W = (const float*)d_in[1];
    float* out = (float*)d_out;

    const size_t shmem = (size_t)(TS*II + II*NN + TS*NN + 2*TS*NN) * sizeof(float); // 221184
    cudaFuncSetAttribute(fused_pass_kernel,
                         cudaFuncAttributeMaxDynamicSharedMemorySize, (int)shmem);

    // it 0: r uniform -> nodes0 from xsum
    xsum_kernel<<<dim3(PP, BB), 512>>>(x);
    nodes_update_kernel<<<dim3(NN, BB), 512>>>(W, 1.0f/32.0f, 1, nullptr);

    // it 1
    fused_pass_kernel<<<dim3(NT, BB), 512, shmem>>>(x, 0);
    nodes_update_kernel<<<dim3(NN, BB), 512>>>(W, 1.0f, 0, nullptr);

    // it 2
    fused_pass_kernel<<<dim3(NT, BB), 512, shmem>>>(x, 1);
    nodes_update_kernel<<<dim3(NN, BB), 512>>>(W, 1.0f, 0, out);
}